// round 1
// baseline (speedup 1.0000x reference)
#include <cuda_runtime.h>

// Problem constants
#define NB    512   // batches
#define NL    512   // stream length (511 increments)
#define NC    8     // channels
#define NCH   8     // stream chunks (Chen-associative split)
#define CHUNK 64    // max increments per chunk
#define SIGSZ 584   // 8 + 64 + 512
#define S2OFF 8
#define S3OFF 72

// Scratch: per-(batch,chunk) truncated signature. ~9.6 MB.
__device__ __align__(16) float g_sig[(size_t)NB * NCH * SIGSZ];

// ---------------------------------------------------------------------------
// Kernel 1: each 64-thread block computes the depth-3 signature of one
// (batch, chunk) path segment. Thread t = i*8+c owns S2[i,c] and S3[i,c,0..7].
// Per-step recurrence (all using OLD state):
//   coef        = dx[i]*dx[c]/6 + S1[i]*dx[c]/2 + S2[i,c]
//   S3[i,c,d]  += coef * dx[d]
//   S2[i,c]    += dx[i]*dx[c]/2 + S1[i]*dx[c]
//   S1[i]      += dx[i]
// ---------------------------------------------------------------------------
__global__ __launch_bounds__(64) void sig_chunk_kernel(const float* __restrict__ path) {
    const int ch = blockIdx.x;
    const int b  = blockIdx.y;
    const int t  = threadIdx.x;          // 0..63
    const int i  = t >> 3;
    const int c  = t & 7;

    __shared__ __align__(16) float sinc[CHUNK * NC];

    const int s0  = ch * CHUNK;
    const int len = min(CHUNK, (NL - 1) - s0);

    const float* prow = path + ((size_t)b * NL + s0) * NC;

    // Precompute increments for this chunk into shared (coalesced float4 loads).
    if (t < len) {
        const float4* p = (const float4*)(prow + (size_t)t * NC);
        float4 a0 = p[0], a1 = p[1];     // row s0+t
        float4 b0 = p[2], b1 = p[3];     // row s0+t+1
        float4* w = (float4*)(sinc + t * NC);
        w[0] = make_float4(b0.x - a0.x, b0.y - a0.y, b0.z - a0.z, b0.w - a0.w);
        w[1] = make_float4(b1.x - a1.x, b1.y - a1.y, b1.z - a1.z, b1.w - a1.w);
    }
    __syncthreads();

    float s1 = 0.f;      // S1[i]
    float s2 = 0.f;      // S2[i,c]
    float s3[8];
    #pragma unroll
    for (int d = 0; d < 8; d++) s3[d] = 0.f;

    #pragma unroll 4
    for (int s = 0; s < len; s++) {
        const float4* r = (const float4*)(sinc + s * NC);
        float4 d0 = r[0];
        float4 d1 = r[1];
        // dynamic channel selects via shared broadcast (no local-mem spill)
        float dxi = sinc[s * NC + i];
        float dxc = sinc[s * NC + c];

        float a    = dxi * dxc;
        float sc   = s1 * dxc;
        float coef = fmaf(a, 1.f / 6.f, fmaf(sc, 0.5f, s2));

        s3[0] = fmaf(coef, d0.x, s3[0]);
        s3[1] = fmaf(coef, d0.y, s3[1]);
        s3[2] = fmaf(coef, d0.z, s3[2]);
        s3[3] = fmaf(coef, d0.w, s3[3]);
        s3[4] = fmaf(coef, d1.x, s3[4]);
        s3[5] = fmaf(coef, d1.y, s3[5]);
        s3[6] = fmaf(coef, d1.z, s3[6]);
        s3[7] = fmaf(coef, d1.w, s3[7]);

        s2 = fmaf(a, 0.5f, s2 + sc);
        s1 += dxi;
    }

    float* out = g_sig + ((size_t)b * NCH + ch) * SIGSZ;
    // S1 of a segment telescopes to endpoint difference.
    if (t < 8) out[t] = prow[(size_t)len * NC + t] - prow[t];
    out[S2OFF + t] = s2;
    float4* o3 = (float4*)(out + S3OFF + t * 8);
    o3[0] = make_float4(s3[0], s3[1], s3[2], s3[3]);
    o3[1] = make_float4(s3[4], s3[5], s3[6], s3[7]);
}

// ---------------------------------------------------------------------------
// Kernel 2: per batch, fold the NCH chunk signatures left-to-right with Chen:
//   C1 = A1 + B1
//   C2[i,c]   = A2 + B2 + A1[i]*B1[c]
//   C3[i,c,d] = A3 + B3 + A1[i]*B2[c,d] + A2[i,c]*B1[d]
// Running signature A lives in registers; thread t = i*8+c.
// ---------------------------------------------------------------------------
__global__ __launch_bounds__(64) void sig_combine_kernel(float* __restrict__ out) {
    const int b = blockIdx.x;
    const int t = threadIdx.x;
    const int i = t >> 3;
    const int c = t & 7;

    const float* base = g_sig + (size_t)b * NCH * SIGSZ;

    __shared__ __align__(16) float B1s[8];

    // Init A = chunk 0 signature.
    if (t < 8) B1s[t] = base[t];
    float a2 = base[S2OFF + t];
    float a3[8];
    {
        const float4* p = (const float4*)(base + S3OFF + t * 8);
        float4 v0 = p[0], v1 = p[1];
        a3[0]=v0.x; a3[1]=v0.y; a3[2]=v0.z; a3[3]=v0.w;
        a3[4]=v1.x; a3[5]=v1.y; a3[6]=v1.z; a3[7]=v1.w;
    }
    __syncthreads();
    float a1i = B1s[i];   // A1[i]
    float a1c = B1s[c];   // A1[c] (tracked for the final level-1 write)

    for (int j = 1; j < NCH; j++) {
        const float* B = base + (size_t)j * SIGSZ;
        __syncthreads();               // protect B1s from previous iteration's readers
        if (t < 8) B1s[t] = B[t];

        float b2t = B[S2OFF + t];      // B2[i,c]
        float b2r[8];                  // B2[c, 0..7]
        {
            const float4* p = (const float4*)(B + S2OFF + c * 8);
            float4 r0 = p[0], r1 = p[1];
            b2r[0]=r0.x; b2r[1]=r0.y; b2r[2]=r0.z; b2r[3]=r0.w;
            b2r[4]=r1.x; b2r[5]=r1.y; b2r[6]=r1.z; b2r[7]=r1.w;
        }
        float b3[8];
        {
            const float4* p = (const float4*)(B + S3OFF + t * 8);
            float4 u0 = p[0], u1 = p[1];
            b3[0]=u0.x; b3[1]=u0.y; b3[2]=u0.z; b3[3]=u0.w;
            b3[4]=u1.x; b3[5]=u1.y; b3[6]=u1.z; b3[7]=u1.w;
        }
        __syncthreads();
        float b1[8];
        {
            float4 lo = *(const float4*)(B1s);
            float4 hi = *(const float4*)(B1s + 4);
            b1[0]=lo.x; b1[1]=lo.y; b1[2]=lo.z; b1[3]=lo.w;
            b1[4]=hi.x; b1[5]=hi.y; b1[6]=hi.z; b1[7]=hi.w;
        }

        #pragma unroll
        for (int d = 0; d < 8; d++)
            a3[d] = fmaf(a2, b1[d], fmaf(a1i, b2r[d], a3[d] + b3[d]));

        float b1c = B1s[c];
        float b1i = B1s[i];
        a2  = fmaf(a1i, b1c, a2 + b2t);   // uses OLD a1i
        a1i += b1i;
        a1c += b1c;
    }

    // Write final signature: [S1(8) | S2(64) | S3(512)]
    float* o = out + (size_t)b * SIGSZ;
    if (t < 8) o[t] = a1c;
    o[S2OFF + t] = a2;
    float4* o3 = (float4*)(o + S3OFF + t * 8);
    o3[0] = make_float4(a3[0], a3[1], a3[2], a3[3]);
    o3[1] = make_float4(a3[4], a3[5], a3[6], a3[7]);
}

extern "C" void kernel_launch(void* const* d_in, const int* in_sizes, int n_in,
                              void* d_out, int out_size) {
    const float* path = (const float*)d_in[0];
    float* out = (float*)d_out;
    sig_chunk_kernel<<<dim3(NCH, NB), 64>>>(path);
    sig_combine_kernel<<<NB, 64>>>(out);
}